// round 12
// baseline (speedup 1.0000x reference)
#include <cuda_runtime.h>
#include <cstdint>

// Problem dims
#define Bb 16384
#define Hh 1024
#define Nn 4096   // 4*H
#define Kk 2048   // D + H

// GEMM tiling: CTA 128x256x32, 8 warps, warp tile 64x64
#define BM 128
#define BN 256
#define BK 32
#define KT (Kk / BK)        // 64
#define STAGES 4
#define A_FLOATS (BM * BK)              // 4096
#define B_FLOATS (BN * BK)              // 8192
#define STAGE_FLOATS (A_FLOATS + B_FLOATS)   // 12288
#define GEMM_SMEM_BYTES (STAGES * STAGE_FLOATS * 4)  // 196608 = 192KB

// Epilogue smem (reuses the stage buffers after the mainloop)
#define BUF_STRIDE 68                   // pad: 68*4 bytes % 16 == 0 (float4-aligned rows)
#define BUF_F (BM * BUF_STRIDE)         // 8704 floats per output buffer

// Scratch (device globals — allocation-free per harness rules)
__device__ float g_A[(size_t)Bb * Kk];     // [x | h], tf32-rounded, K-major
__device__ float g_W[(size_t)Nn * Kk];     // gate-interleaved [Wi|Wh], tf32, K-major

__device__ __forceinline__ float rna_tf32(float v) {
    uint32_t u; asm("cvt.rna.tf32.f32 %0, %1;" : "=r"(u) : "f"(v));
    return __uint_as_float(u);
}

// ---------------------------------------------------------------------------
// Pack kernels: concatenate along K, RNA-round to tf32.
// pack_W additionally interleaves gates: output row n' = h*4 + gate.
// ---------------------------------------------------------------------------
__global__ void pack_A(const float* __restrict__ x, const float* __restrict__ h) {
    size_t i = (size_t)blockIdx.x * blockDim.x + threadIdx.x;
    size_t b = i >> 9;
    int k4 = (int)(i & 511);
    float4 v = (k4 < 256) ? reinterpret_cast<const float4*>(x + b * 1024)[k4]
                          : reinterpret_cast<const float4*>(h + b * 1024)[k4 - 256];
    float4 o;
    o.x = rna_tf32(v.x); o.y = rna_tf32(v.y); o.z = rna_tf32(v.z); o.w = rna_tf32(v.w);
    reinterpret_cast<float4*>(g_A)[i] = o;
}
__global__ void pack_W(const float* __restrict__ Wi, const float* __restrict__ Wh) {
    size_t i = (size_t)blockIdx.x * blockDim.x + threadIdx.x;
    size_t np = i >> 9;                      // interleaved row n' = h*4 + gate
    int k4 = (int)(i & 511);
    size_t gate = np & 3, hh = np >> 2;
    size_t src_row = gate * 1024 + hh;       // row in [4096,1024] flatten of Wi/Wh
    float4 v = (k4 < 256)
        ? reinterpret_cast<const float4*>(Wi + src_row * 1024)[k4]
        : reinterpret_cast<const float4*>(Wh + src_row * 1024)[k4 - 256];
    float4 o;
    o.x = rna_tf32(v.x); o.y = rna_tf32(v.y); o.z = rna_tf32(v.z); o.w = rna_tf32(v.w);
    reinterpret_cast<float4*>(g_W)[i] = o;
}

// ---------------------------------------------------------------------------
// TF32 mma.sync GEMM + fused LSTM epilogue
// pre = g_A (16384x2048) * g_W^T (2048x4096, gate-interleaved cols)
// ---------------------------------------------------------------------------
__device__ __forceinline__ int swz(int r, int c) {
    return r * BK + (c ^ ((r & 7) << 2));
}
__device__ __forceinline__ void cp16(uint32_t s, const float* g) {
    asm volatile("cp.async.cg.shared.global [%0], [%1], 16;" :: "r"(s), "l"(g));
}
__device__ __forceinline__ void cp_commit() { asm volatile("cp.async.commit_group;"); }
template <int N>
__device__ __forceinline__ void cp_wait() { asm volatile("cp.async.wait_group %0;" :: "n"(N)); }

__device__ __forceinline__ float sigm(float x) { return 1.f / (1.f + __expf(-x)); }
__device__ __forceinline__ float tanh_f(float x) { return 2.f * sigm(2.f * x) - 1.f; }

__global__ void __launch_bounds__(256, 1) gemm_lstm(
    const float* __restrict__ cin, const float* __restrict__ bi,
    float* __restrict__ out, int out_size)
{
    extern __shared__ float smem[];
    uint32_t smem_u;
    asm("{ .reg .u64 t; cvta.to.shared.u64 t, %1; cvt.u32.u64 %0, t; }"
        : "=r"(smem_u) : "l"(smem));

    // Band schedule: ntile inner -> one wave shares A band + all of W in L2.
    int bid = blockIdx.x;
    int ntile = bid & 15;     // 16 n-tiles of 256 (= 64 h x 4 gates)
    int mtile = bid >> 4;     // 128 m-tiles of 128

    int tid = threadIdx.x;
    int lane = tid & 31, warp = tid >> 5;
    int wm = warp & 1, wn = warp >> 1;    // 2 x 4 warp grid, warp tile 64x64
    int rq = lane >> 2, cq = lane & 3;

    const float* gA = g_A + (size_t)mtile * BM * Kk;
    const float* gB = g_W + (size_t)ntile * BN * Kk;

    float acc[4][8][4];
#pragma unroll
    for (int i = 0; i < 4; i++)
#pragma unroll
        for (int j = 0; j < 8; j++)
#pragma unroll
            for (int l = 0; l < 4; l++) acc[i][j][l] = 0.f;

    auto load_stage = [&](int s, int kt) {
        uint32_t as = smem_u + (uint32_t)(s * STAGE_FLOATS) * 4;
        uint32_t bs = as + A_FLOATS * 4;
#pragma unroll
        for (int i = 0; i < 4; i++) {
            int ch = i * 256 + tid;
            int row = ch >> 3, c = ch & 7;
            cp16(as + (uint32_t)swz(row, c * 4) * 4,
                 gA + (size_t)row * Kk + kt * BK + c * 4);
        }
#pragma unroll
        for (int i = 0; i < 8; i++) {
            int ch = i * 256 + tid;
            int row = ch >> 3, c = ch & 7;
            cp16(bs + (uint32_t)swz(row, c * 4) * 4,
                 gB + (size_t)row * Kk + kt * BK + c * 4);
        }
    };

#pragma unroll
    for (int s = 0; s < STAGES - 1; s++) { load_stage(s, s); cp_commit(); }

    for (int kt = 0; kt < KT; kt++) {
        int rem = KT - 1 - kt;
        if (rem >= STAGES - 1) cp_wait<STAGES - 2>();
        else if (rem == 2)     cp_wait<2>();
        else if (rem == 1)     cp_wait<1>();
        else                   cp_wait<0>();
        __syncthreads();

        int pf = kt + STAGES - 1;
        if (pf < KT) { load_stage(pf & (STAGES - 1), pf); cp_commit(); }

        const float* as = smem + (kt & (STAGES - 1)) * STAGE_FLOATS;
        const float* bs = as + A_FLOATS;

#pragma unroll
        for (int k8 = 0; k8 < 4; k8++) {
            int k0 = k8 * 8 + cq;
            uint32_t a[4][4], b[8][2];
#pragma unroll
            for (int mi = 0; mi < 4; mi++) {
                int r = wm * 64 + mi * 16 + rq;
                a[mi][0] = __float_as_uint(as[swz(r,     k0)]);
                a[mi][1] = __float_as_uint(as[swz(r + 8, k0)]);
                a[mi][2] = __float_as_uint(as[swz(r,     k0 + 4)]);
                a[mi][3] = __float_as_uint(as[swz(r + 8, k0 + 4)]);
            }
#pragma unroll
            for (int ni = 0; ni < 8; ni++) {
                int rn = wn * 64 + ni * 8 + rq;
                b[ni][0] = __float_as_uint(bs[swz(rn, k0)]);
                b[ni][1] = __float_as_uint(bs[swz(rn, k0 + 4)]);
            }
#pragma unroll
            for (int mi = 0; mi < 4; mi++)
#pragma unroll
                for (int ni = 0; ni < 8; ni++) {
                    float* c = acc[mi][ni];
                    asm volatile(
                        "mma.sync.aligned.m16n8k8.row.col.f32.tf32.tf32.f32 "
                        "{%0,%1,%2,%3}, {%4,%5,%6,%7}, {%8,%9}, {%0,%1,%2,%3};"
                        : "+f"(c[0]), "+f"(c[1]), "+f"(c[2]), "+f"(c[3])
                        : "r"(a[mi][0]), "r"(a[mi][1]), "r"(a[mi][2]), "r"(a[mi][3]),
                          "r"(b[ni][0]), "r"(b[ni][1]));
                }
        }
    }

    // ================= fused LSTM epilogue =================
    // CTA owns rows [mtile*128, +128) x h [ntile*64, +64), all 4 gates.
    __syncthreads();                       // stage buffers now reusable

    float* buf_o  = smem;
    float* buf_nh = smem + BUF_F;
    float* buf_nc = smem + 2 * BUF_F;
    float* bias_s = smem + 3 * BUF_F;      // 256 floats: [h_loc*4 + gate]

    int h0 = ntile * 64;
    bias_s[tid] = bi[(size_t)(tid & 3) * 1024 + h0 + (tid >> 2)];
    __syncthreads();

    size_t mbase = (size_t)mtile * BM;
    int parity = cq & 1;                   // even lane -> row rq, odd -> rq+8

#pragma unroll
    for (int mi = 0; mi < 4; mi++) {
        int rloc = wm * 64 + mi * 16 + rq + 8 * parity;
        const float* crow = cin + (mbase + rloc) * Hh + h0;
#pragma unroll
        for (int ni = 0; ni < 8; ni++) {
            float v0 = acc[mi][ni][0], v1 = acc[mi][ni][1];
            float v2 = acc[mi][ni][2], v3 = acc[mi][ni][3];
            float t0 = __shfl_xor_sync(0xffffffffu, v0, 1);
            float t1 = __shfl_xor_sync(0xffffffffu, v1, 1);
            float t2 = __shfl_xor_sync(0xffffffffu, v2, 1);
            float t3 = __shfl_xor_sync(0xffffffffu, v3, 1);
            // even lane: my (v0,v1)=gates(i,f)@row rq, partner (t0,t1)=gates(g,o)@row rq
            // odd lane:  partner (t2,t3)=gates(i,f)@row rq+8, my (v2,v3)=gates(g,o)@row rq+8
            float p_i = parity ? t2 : v0;
            float p_f = parity ? t3 : v1;
            float p_g = parity ? v2 : t0;
            float p_o = parity ? v3 : t1;

            int h_l = wn * 16 + ni * 2 + (cq >> 1);
            const float* bs4 = bias_s + h_l * 4;
            float gi = sigm(p_i + bs4[0]);
            float gf = sigm(p_f + bs4[1]);
            float gg = tanh_f(p_g + bs4[2]);
            float gO = sigm(p_o + bs4[3]);

            float cv = __ldg(crow + h_l);
            float nc = gf * cv + gi * gg;
            float nh = gO * tanh_f(nc);

            int bidx = rloc * BUF_STRIDE + h_l;
            buf_o[bidx]  = gO;
            buf_nh[bidx] = nh;
            buf_nc[bidx] = nc;
        }
    }
    __syncthreads();

    // Coalesced float4 stores: 128 rows x 64 h per CTA, 2048 float4 per output.
    bool full = (out_size >= 3 * (int)(Bb) * Hh / 1);  // 3*B*H fits? use 64-bit-safe compare below
    size_t BH = (size_t)Bb * Hh;
    bool has3 = ((size_t)out_size >= 3 * BH);
#pragma unroll
    for (int it = 0; it < 8; it++) {
        int fi = it * 256 + tid;           // [0, 2048)
        int r = fi >> 4, q = fi & 15;
        size_t g = (mbase + r) * Hh + h0 + q * 4;
        float4 vo = *reinterpret_cast<float4*>(buf_o  + r * BUF_STRIDE + q * 4);
        *reinterpret_cast<float4*>(out + g) = vo;
        if (has3) {
            float4 vh = *reinterpret_cast<float4*>(buf_nh + r * BUF_STRIDE + q * 4);
            float4 vc = *reinterpret_cast<float4*>(buf_nc + r * BUF_STRIDE + q * 4);
            *reinterpret_cast<float4*>(out + BH + g)     = vh;
            *reinterpret_cast<float4*>(out + 2 * BH + g) = vc;
        }
    }
    (void)full;
}

// ---------------------------------------------------------------------------
// Launch: pack -> fused GEMM+LSTM (graph-capturable)
// ---------------------------------------------------------------------------
extern "C" void kernel_launch(void* const* d_in, const int* in_sizes, int n_in,
                              void* d_out, int out_size) {
    const float* x  = (const float*)d_in[0];
    const float* h  = (const float*)d_in[1];
    const float* c  = (const float*)d_in[2];
    const float* Wi = (const float*)d_in[3];
    const float* bi = (const float*)d_in[4];
    const float* Wh = (const float*)d_in[5];
    float* out = (float*)d_out;

    pack_A<<<32768, 256>>>(x, h);
    pack_W<<<8192, 256>>>(Wi, Wh);

    cudaFuncSetAttribute(gemm_lstm, cudaFuncAttributeMaxDynamicSharedMemorySize,
                         GEMM_SMEM_BYTES);
    gemm_lstm<<<(Bb / BM) * (Nn / BN), 256, GEMM_SMEM_BYTES>>>(c, bi, out, out_size);
}